// round 6
// baseline (speedup 1.0000x reference)
#include <cuda_runtime.h>
#include <math.h>

// Problem constants (B=4, T=2048, D=1024, E=8, K=2)
#define BT           8192
#define DD           1024
#define EE           8
#define TPB          256
#define ROWS_PER_CTA 16
#define NCTA         (BT / ROWS_PER_CTA)   // 512
#define CROWS        4                     // rows per combine CTA
#define NCCTA        (BT / CROWS)          // 2048

__device__ float        g_aux_part[NCTA];
__device__ unsigned int g_ctr;             // zero-init; self-resets each launch
__device__ int2         g_idx[BT];         // selected (i0,i1) per row

// ============================ Kernel A: gating ============================
__global__ __launch_bounds__(TPB) void rlgate_gate_kernel(
    const float* __restrict__ x,          // [BT, D]
    const float* __restrict__ rewards,    // [BT]
    const float* __restrict__ W,          // [D, E]
    const float* __restrict__ bias,       // [E]
    const float* __restrict__ baseline,   // scalar
    const float* __restrict__ noise,      // [BT, E]
    float* __restrict__ out,              // aux slot at out[out_size-1]
    int out_size)
{
    __shared__ float Wt[EE][DD];          // transposed gate weights, 32KB
    __shared__ float s_aux[ROWS_PER_CTA];

    const int tid  = threadIdx.x;
    const int lane = tid & 31;
    const int warp = tid >> 5;

    const int r0 = blockIdx.x * ROWS_PER_CTA + warp * 2;
    const int r1 = r0 + 1;

    const float4* x0 = (const float4*)(x + (size_t)r0 * DD);
    const float4* x1 = (const float4*)(x + (size_t)r1 * DD);

    // Prefetch first 2 x-iterations BEFORE the smem barrier (overlaps W fill).
    float4 xa0 = __ldg(x0 + lane);
    float4 xb0 = __ldg(x1 + lane);
    float4 xa1 = __ldg(x0 + lane + 32);
    float4 xb1 = __ldg(x1 + lane + 32);

    // ---- Load W [D,E] -> smem transposed Wt[E][D] (vectorized) ----
    {
        const float4* W4 = (const float4*)W;
#pragma unroll
        for (int k = 0; k < (DD * EE / 4) / TPB; k++) {
            int i = tid + k * TPB;
            float4 v = __ldg(W4 + i);
            int d  = i >> 1;
            int e0 = (i & 1) * 4;
            Wt[e0 + 0][d] = v.x;
            Wt[e0 + 1][d] = v.y;
            Wt[e0 + 2][d] = v.z;
            Wt[e0 + 3][d] = v.w;
        }
    }
    __syncthreads();

    // ---- Phase 1: logits for both rows (depth-2 pipelined) ----
    float acc0[EE], acc1[EE];
#pragma unroll
    for (int e = 0; e < EE; e++) { acc0[e] = 0.0f; acc1[e] = 0.0f; }

    const float4* Wt4 = (const float4*)Wt;   // Wt4[e*256 + j]

#pragma unroll
    for (int i = 0; i < 8; i++) {
        float4 a4 = (i & 1) ? xa1 : xa0;
        float4 b4 = (i & 1) ? xb1 : xb0;
        if (i < 6) {                          // prefetch i+2
            int jn = lane + 32 * (i + 2);
            if (i & 1) { xa1 = __ldg(x0 + jn); xb1 = __ldg(x1 + jn); }
            else       { xa0 = __ldg(x0 + jn); xb0 = __ldg(x1 + jn); }
        }
        int j = lane + 32 * i;
#pragma unroll
        for (int e = 0; e < EE; e++) {
            float4 w = Wt4[e * (DD / 4) + j];
            acc0[e] = fmaf(a4.x, w.x, fmaf(a4.y, w.y, fmaf(a4.z, w.z, fmaf(a4.w, w.w, acc0[e]))));
            acc1[e] = fmaf(b4.x, w.x, fmaf(b4.y, w.y, fmaf(b4.z, w.z, fmaf(b4.w, w.w, acc1[e]))));
        }
    }

#pragma unroll
    for (int e = 0; e < EE; e++) {
#pragma unroll
        for (int off = 16; off > 0; off >>= 1) {
            acc0[e] += __shfl_xor_sync(0xffffffffu, acc0[e], off);
            acc1[e] += __shfl_xor_sync(0xffffffffu, acc1[e], off);
        }
    }

    // ---- Phase 2: lanes 0/1 do softmax -> gumbel top-2 for r0/r1 ----
    {
        float a[EE];
#pragma unroll
        for (int e = 0; e < EE; e++) a[e] = (lane == 1) ? acc1[e] : acc0[e];
        const int row = (lane == 1) ? r1 : r0;

        if (lane < 2) {
            float l[EE];
            float m = -1e30f;
#pragma unroll
            for (int e = 0; e < EE; e++) { l[e] = a[e] + __ldg(bias + e); m = fmaxf(m, l[e]); }
            float p[EE];
            float sum = 0.0f;
#pragma unroll
            for (int e = 0; e < EE; e++) { p[e] = __expf(l[e] - m); sum += p[e]; }
            float inv = 1.0f / sum;
            float lp[EE];
#pragma unroll
            for (int e = 0; e < EE; e++) lp[e] = logf(p[e] * inv + 1e-9f);

            const float* nu = noise + (size_t)row * EE;
            float y[EE];
#pragma unroll
            for (int e = 0; e < EE; e++) {
                float u = __ldg(nu + e) * (1.0f - 2e-7f) + 1e-7f;
                y[e] = lp[e] - logf(-logf(u));
            }
            int i0 = 0;
#pragma unroll
            for (int e = 1; e < EE; e++) if (y[e] > y[i0]) i0 = e;
            int i1 = (i0 == 0) ? 1 : 0;
#pragma unroll
            for (int e = 0; e < EE; e++) if (e != i0 && y[e] > y[i1]) i1 = e;

            g_idx[row] = make_int2(i0, i1);

            float adv = __ldg(rewards + row) - __ldg(baseline);
            s_aux[warp * 2 + lane] = adv * (lp[i0] + lp[i1]);
        }
    }

    // ---- Aux partial + last-CTA finale (deterministic reduction order) ----
    __syncthreads();
    if (warp == 0) {
        int is_last = 0;
        if (lane == 0) {
            float s = 0.0f;
#pragma unroll
            for (int i = 0; i < ROWS_PER_CTA; i++) s += s_aux[i];
            g_aux_part[blockIdx.x] = s;
            __threadfence();
            unsigned p = atomicAdd(&g_ctr, 1u);
            is_last = (p == NCTA - 1);
        }
        is_last = __shfl_sync(0xffffffffu, is_last, 0);
        if (is_last) {
            double s = 0.0;
#pragma unroll
            for (int k = 0; k < NCTA / 32; k++)
                s += (double)__ldcg(&g_aux_part[lane + 32 * k]);
#pragma unroll
            for (int off = 16; off > 0; off >>= 1)
                s += __shfl_xor_sync(0xffffffffu, s, off);
            if (lane == 0) {
                out[out_size - 1] = -(float)(s / (double)BT);
                g_ctr = 0;                    // reset for next graph replay
            }
        }
    }
}

// ========================== Kernel B: combine ============================
// Pure streaming gather-average: 4 rows per CTA, 256 threads, one float4
// position per thread per row. No smem weights, tiny register footprint.
__global__ __launch_bounds__(TPB) void rlgate_combine_kernel(
    const float* __restrict__ eo,         // [E, BT, D]
    float* __restrict__ out)              // [BT, D]
{
    __shared__ int2 s_idx[CROWS];

    const int tid  = threadIdx.x;
    const int base = blockIdx.x * CROWS;

    if (tid < CROWS) s_idx[tid] = g_idx[base + tid];
    __syncthreads();

#pragma unroll
    for (int r = 0; r < CROWS; r++) {
        const int row = base + r;
        const int2 ii = s_idx[r];
        const float4* pa = (const float4*)(eo + ((size_t)ii.x * BT + row) * DD);
        const float4* pb = (const float4*)(eo + ((size_t)ii.y * BT + row) * DD);
        float4* o = (float4*)(out + (size_t)row * DD);

        float4 va = __ldcs(pa + tid);
        float4 vb = __ldcs(pb + tid);
        float4 rv;
        rv.x = (va.x + vb.x) * 0.5f;
        rv.y = (va.y + vb.y) * 0.5f;
        rv.z = (va.z + vb.z) * 0.5f;
        rv.w = (va.w + vb.w) * 0.5f;
        __stcs(o + tid, rv);
    }
}

extern "C" void kernel_launch(void* const* d_in, const int* in_sizes, int n_in,
                              void* d_out, int out_size) {
    const float* x        = (const float*)d_in[0];
    const float* eo       = (const float*)d_in[1];
    const float* rewards  = (const float*)d_in[2];
    const float* W        = (const float*)d_in[3];
    const float* bias     = (const float*)d_in[4];
    const float* baseline = (const float*)d_in[5];
    const float* noise    = (const float*)d_in[6];
    // d_in[7] = top_k (K=2 hardcoded to match problem shapes)
    float* out = (float*)d_out;

    rlgate_gate_kernel<<<NCTA, TPB>>>(x, rewards, W, bias, baseline, noise,
                                      out, out_size);
    rlgate_combine_kernel<<<NCCTA, TPB>>>(eo, out);
}